// round 15
// baseline (speedup 1.0000x reference)
#include <cuda_runtime.h>

// Problem constants (N_ATOMS = 128, fixed by the reference)
#define NA      128
#define NSEG    7875          // sum_{i=0}^{124} (125 - i)
#define OUTPB   16256         // n^2 - n  (all off-diagonal cells, row-major)
#define MAXB    512
#define SDIM    130           // padded symmetric matrix, zero border (520B rows: benign L2 hash)

// Scratch: per-batch padded symmetric segment-writhe matrix (~34.6 MB).
// Zero-initialized at module load. writhe writes valid (|i-j|>=2) cells in
// BOTH triangles; all other cells stay 0 forever.
__device__ float g_S[(size_t)MAXB * SDIM * SDIM];

// Branch-free asin via Abramowitz & Stegun 4.4.45 (|eps| <= 6.8e-5 abs).
// Saturates for |x| slightly > 1: no clamp needed.
__device__ __forceinline__ float fast_asin(float x)
{
    const float a = fabsf(x);
    float p = fmaf(a, -0.0187293f, 0.0742610f);
    p = fmaf(a, p, -0.2121144f);
    p = fmaf(a, p,  1.5707288f);
    const float om = fmaxf(1.0f - a, 1e-38f);
    const float s  = om * rsqrtf(om);                // sqrt(om) via MUFU
    return copysignf(1.5707963268f - s * p, x);
}

// -------------------------------------------------------------------------
// Kernel 1: writhe, 4 chained segments per thread (one row, j0..j0+3).
// Warp packing: warp 0 <-> row 0; warp p (1..62) packs rows (p, 125-p)
// whose quad counts sum to exactly 32. 63 warps per batch.
// Chain identities per j -> j+1:  d0 <- d1, d2 <- d3, c3 <- -c1, r3 <- r1.
// (R11 body, verbatim — measured ~30.5us.)
// -------------------------------------------------------------------------
__global__ __launch_bounds__(256) void writhe_kernel(const float* __restrict__ xyz)
{
    __shared__ float4 pt[NA];
    const int b = blockIdx.y;
    const float* x = xyz + (size_t)b * NA * 3;
    for (int t = threadIdx.x; t < NA; t += blockDim.x)
        pt[t] = make_float4(x[3 * t + 0], x[3 * t + 1], x[3 * t + 2], 0.0f);
    __syncthreads();

    const int warp = threadIdx.x >> 5;
    const int lane = threadIdx.x & 31;
    const int p    = blockIdx.x * 8 + warp;          // 0..63; 63 is empty
    if (p > 62) return;

    const int iA = p;
    const int iB = (p == 0) ? 0 : (125 - p);
    const int qA = (125 - iA + 3) >> 2;              // quads in row A (<=32)

    const bool inA = (lane < qA);
    const int  i   = inA ? iA : iB;
    const int  m   = inA ? lane : (lane - qA);
    const int  j0  = i + 2 + 4 * m;

    const float4 Q0 = pt[i];
    const float4 Q1 = pt[i + 1];
    float4 Pj[5];
    #pragma unroll
    for (int k = 0; k < 5; ++k) Pj[k] = pt[min(j0 + k, 127)];

    // chain state: d0 = P_j - P_i, d2 = P_j - P_{i+1}, c3 = d2 x d0
    float d0x = Pj[0].x - Q0.x, d0y = Pj[0].y - Q0.y, d0z = Pj[0].z - Q0.z;
    float d2x = Pj[0].x - Q1.x, d2y = Pj[0].y - Q1.y, d2z = Pj[0].z - Q1.z;
    float c3x = d2y * d0z - d2z * d0y;
    float c3y = d2z * d0x - d2x * d0z;
    float c3z = d2x * d0y - d2y * d0x;
    float r3  = rsqrtf(c3x * c3x + c3y * c3y + c3z * c3z);

    float* S = g_S + (size_t)b * SDIM * SDIM;

    #pragma unroll
    for (int k = 0; k < 4; ++k) {
        const int j = j0 + k;
        const float4 Pn = Pj[k + 1];

        const float d1x = Pn.x - Q0.x, d1y = Pn.y - Q0.y, d1z = Pn.z - Q0.z;
        const float d3x = Pn.x - Q1.x, d3y = Pn.y - Q1.y, d3z = Pn.z - Q1.z;

        // c0 = d0 x d1, c1 = d1 x d3, c2 = d3 x d2
        const float c0x = d0y * d1z - d0z * d1y;
        const float c0y = d0z * d1x - d0x * d1z;
        const float c0z = d0x * d1y - d0y * d1x;

        const float c1x = d1y * d3z - d1z * d3y;
        const float c1y = d1z * d3x - d1x * d3z;
        const float c1z = d1x * d3y - d1y * d3x;

        const float c2x = d3y * d2z - d3z * d2y;
        const float c2y = d3z * d2x - d3x * d2z;
        const float c2z = d3x * d2y - d3y * d2x;

        // sign: dot(axial, d0) == -(d2 . c0)
        const float dp = d2x * c0x + d2y * c0y + d2z * c0z;
        const float sg = (dp < 0.0f) ? 1.0f : ((dp > 0.0f) ? -1.0f : 0.0f);

        const float r0 = rsqrtf(c0x * c0x + c0y * c0y + c0z * c0z);
        const float r1 = rsqrtf(c1x * c1x + c1y * c1y + c1z * c1z);
        const float r2 = rsqrtf(c2x * c2x + c2y * c2y + c2z * c2z);

        // no clamps: fast_asin saturates for |q| slightly > 1
        const float q0 = (c0x * c1x + c0y * c1y + c0z * c1z) * r0 * r1;
        const float q1 = (c1x * c2x + c1y * c2y + c1z * c2z) * r1 * r2;
        const float q2 = (c2x * c3x + c2y * c3y + c2z * c3z) * r2 * r3;
        const float q3 = (c3x * c0x + c3y * c0y + c3z * c0z) * r3 * r0;

        const float omega = fast_asin(q0) + fast_asin(q1) +
                            fast_asin(q2) + fast_asin(q3);
        const float wr = omega * sg * 0.15915494309189535f; // 1/(2*pi)

        if (j <= 126) {
            S[(i + 1) * SDIM + (j + 1)] = wr;
            S[(j + 1) * SDIM + (i + 1)] = wr;
        }

        // rotate chain state
        d0x = d1x;  d0y = d1y;  d0z = d1z;
        d2x = d3x;  d2y = d3y;  d2z = d3z;
        c3x = -c1x; c3y = -c1y; c3z = -c1z;
        r3  = r1;
    }
}

// -------------------------------------------------------------------------
// Kernel 2: stencil via staged vertical-pair sums.
// Block <-> 2048 consecutive k of one batch (8 blocks per batch).
//   T_r[c] = S[r][c] + S[r+1][c]   staged as float2 (row stride 65 float2)
//   out[k] = T_r[c] + T_r[c+1]     lane-strided scalar outputs (conflict-free)
// One true division per thread; (r, cp) tracked incrementally.
// -------------------------------------------------------------------------
__global__ __launch_bounds__(256) void gather_kernel(float* __restrict__ out)
{
    __shared__ float T[18 * SDIM];
    const int b    = blockIdx.y;
    const int k0   = blockIdx.x << 11;                   // 2048 k per block
    const int kend = min(k0 + 2048, OUTPB);
    const int r_first = k0 / 127;
    const int r_last  = (kend - 1) / 127;
    const int n2      = ((r_last - r_first + 1) * SDIM) >> 1;   // float2 count

    // float2 staging: row stride 130 floats = 65 float2; batch offset even.
    const float2* Sg2 = (const float2*)(g_S + (size_t)b * SDIM * SDIM
                                            + (size_t)r_first * SDIM);
    float2* T2 = (float2*)T;
    for (int idx = threadIdx.x; idx < n2; idx += 256) {
        const float2 a  = Sg2[idx];
        const float2 bb = Sg2[idx + (SDIM >> 1)];
        T2[idx] = make_float2(a.x + bb.x, a.y + bb.y);
    }
    __syncthreads();

    float* ob = out + (size_t)b * OUTPB;

    int k  = k0 + threadIdx.x;
    int r  = k / 127;                                    // one division total
    int cp = k - r * 127;

    #pragma unroll
    for (int m = 0; m < 8; ++m) {
        if (k < kend) {
            const int c = cp + (cp >= r ? 1 : 0);
            const float* Trow = T + (r - r_first) * SDIM;
            ob[k] = Trow[c] + Trow[c + 1];
        }
        // k += 256 == 2*127 + 2  ->  r += 2, cp += 2 (one wrap max)
        k += 256; r += 2; cp += 2;
        if (cp >= 127) { cp -= 127; ++r; }
    }
}

// -------------------------------------------------------------------------
extern "C" void kernel_launch(void* const* d_in, const int* in_sizes, int n_in,
                              void* d_out, int out_size)
{
    const float* xyz = (const float*)d_in[0];
    int B = in_sizes[0] / (NA * 3);
    if (B > MAXB) B = MAXB;

    dim3 gw(8, B);                      // 8 blocks x 8 warps = 64 warps (63 used)
    writhe_kernel<<<gw, 256>>>(xyz);

    dim3 gg(8, B);                      // 8 x 2048 k-chunks
    gather_kernel<<<gg, 256>>>((float*)d_out);
}

// round 16
// speedup vs baseline: 1.4192x; 1.4192x over previous
#include <cuda_runtime.h>

// Problem constants (N_ATOMS = 128, fixed by the reference)
#define NA      128
#define NSEG    7875          // sum_{i=0}^{124} (125 - i)
#define OUTPB   16256         // n^2 - n  (all off-diagonal cells, row-major)
#define MAXB    512
#define SDIM    130           // padded symmetric matrix, zero border (520B rows: benign L2 hash)

// Scratch: per-batch padded symmetric segment-writhe matrix (~34.6 MB).
// Zero-initialized at module load. writhe writes valid (|i-j|>=2) cells in
// BOTH triangles; all other cells stay 0 forever.
__device__ float g_S[(size_t)MAXB * SDIM * SDIM];

// Branch-free asin/(2*pi) via Abramowitz & Stegun 4.4.45 (|eps| <= 6.8e-5 abs
// pre-scale). All constants pre-multiplied by 1/(2*pi) = 0.15915494; positive
// scaling commutes with copysignf, so this returns asin(x)/(2*pi) exactly in
// the same instruction shape. Saturates for |x| slightly > 1: no clamp needed.
__device__ __forceinline__ float fast_asin_c(float x)
{
    const float a = fabsf(x);
    float p = fmaf(a, -0.0029805f, 0.0118195f);      // -0.0187293/2pi, 0.0742610/2pi
    p = fmaf(a, p, -0.0337608f);                     // -0.2121144/2pi
    p = fmaf(a, p,  0.2499893f);                     //  1.5707288/2pi
    const float om = fmaxf(1.0f - a, 1e-38f);
    const float s  = om * rsqrtf(om);                // sqrt(om) via MUFU
    return copysignf(0.25f - s * p, x);              // pi/2 / (2*pi) = 0.25
}

// -------------------------------------------------------------------------
// Kernel 1: writhe, 4 chained segments per thread (one row, j0..j0+3).
// Warp packing: warp 0 <-> row 0; warp p (1..62) packs rows (p, 125-p)
// whose quad counts sum to exactly 32. 63 warps per batch.
// Chain identities per j -> j+1:  d0 <- d1, d2 <- d3, c3 <- -c1, r3 <- r1.
// (R11 body, measured ~30.5us @ issue 85%.)
// -------------------------------------------------------------------------
__global__ __launch_bounds__(256) void writhe_kernel(const float* __restrict__ xyz)
{
    __shared__ float4 pt[NA];
    const int b = blockIdx.y;
    const float* x = xyz + (size_t)b * NA * 3;
    for (int t = threadIdx.x; t < NA; t += blockDim.x)
        pt[t] = make_float4(x[3 * t + 0], x[3 * t + 1], x[3 * t + 2], 0.0f);
    __syncthreads();

    const int warp = threadIdx.x >> 5;
    const int lane = threadIdx.x & 31;
    const int p    = blockIdx.x * 8 + warp;          // 0..63; 63 is empty
    if (p > 62) return;

    const int iA = p;
    const int iB = (p == 0) ? 0 : (125 - p);
    const int qA = (125 - iA + 3) >> 2;              // quads in row A (<=32)

    const bool inA = (lane < qA);
    const int  i   = inA ? iA : iB;
    const int  m   = inA ? lane : (lane - qA);
    const int  j0  = i + 2 + 4 * m;

    const float4 Q0 = pt[i];
    const float4 Q1 = pt[i + 1];
    float4 Pj[5];
    #pragma unroll
    for (int k = 0; k < 5; ++k) Pj[k] = pt[min(j0 + k, 127)];

    // chain state: d0 = P_j - P_i, d2 = P_j - P_{i+1}, c3 = d2 x d0
    float d0x = Pj[0].x - Q0.x, d0y = Pj[0].y - Q0.y, d0z = Pj[0].z - Q0.z;
    float d2x = Pj[0].x - Q1.x, d2y = Pj[0].y - Q1.y, d2z = Pj[0].z - Q1.z;
    float c3x = d2y * d0z - d2z * d0y;
    float c3y = d2z * d0x - d2x * d0z;
    float c3z = d2x * d0y - d2y * d0x;
    float r3  = rsqrtf(c3x * c3x + c3y * c3y + c3z * c3z);

    float* S = g_S + (size_t)b * SDIM * SDIM;

    #pragma unroll
    for (int k = 0; k < 4; ++k) {
        const int j = j0 + k;
        const float4 Pn = Pj[k + 1];

        const float d1x = Pn.x - Q0.x, d1y = Pn.y - Q0.y, d1z = Pn.z - Q0.z;
        const float d3x = Pn.x - Q1.x, d3y = Pn.y - Q1.y, d3z = Pn.z - Q1.z;

        // c0 = d0 x d1, c1 = d1 x d3, c2 = d3 x d2
        const float c0x = d0y * d1z - d0z * d1y;
        const float c0y = d0z * d1x - d0x * d1z;
        const float c0z = d0x * d1y - d0y * d1x;

        const float c1x = d1y * d3z - d1z * d3y;
        const float c1y = d1z * d3x - d1x * d3z;
        const float c1z = d1x * d3y - d1y * d3x;

        const float c2x = d3y * d2z - d3z * d2y;
        const float c2y = d3z * d2x - d3x * d2z;
        const float c2z = d3x * d2y - d3y * d2x;

        // sign: dot(axial, d0) == -(d2 . c0)
        const float dp = d2x * c0x + d2y * c0y + d2z * c0z;
        const float sg = (dp < 0.0f) ? 1.0f : ((dp > 0.0f) ? -1.0f : 0.0f);

        const float r0 = rsqrtf(c0x * c0x + c0y * c0y + c0z * c0z);
        const float r1 = rsqrtf(c1x * c1x + c1y * c1y + c1z * c1z);
        const float r2 = rsqrtf(c2x * c2x + c2y * c2y + c2z * c2z);

        // no clamps: fast_asin_c saturates for |q| slightly > 1
        const float q0 = (c0x * c1x + c0y * c1y + c0z * c1z) * r0 * r1;
        const float q1 = (c1x * c2x + c1y * c2y + c1z * c2z) * r1 * r2;
        const float q2 = (c2x * c3x + c2y * c3y + c2z * c3z) * r2 * r3;
        const float q3 = (c3x * c0x + c3y * c0y + c3z * c0z) * r3 * r0;

        // omega/(2*pi), then just multiply by the sign
        const float wr = (fast_asin_c(q0) + fast_asin_c(q1) +
                          fast_asin_c(q2) + fast_asin_c(q3)) * sg;

        if (j <= 126) {
            S[(i + 1) * SDIM + (j + 1)] = wr;
            S[(j + 1) * SDIM + (i + 1)] = wr;
        }

        // rotate chain state
        d0x = d1x;  d0y = d1y;  d0z = d1z;
        d2x = d3x;  d2y = d3y;  d2z = d3z;
        c3x = -c1x; c3y = -c1y; c3z = -c1z;
        r3  = r1;
    }
}

// -------------------------------------------------------------------------
// Kernel 2: stencil via staged vertical-pair sums (R11 body, verbatim —
// measured 17.4us).
// Block <-> 1024 consecutive k of one batch. Stage T rows:
//   T_r[c] = S[r][c] + S[r+1][c]     (identical layout -> coalesced staging)
// Then out[k] = T_r[c] + T_r[c+1], threads lane-strided over k.
// (r, cp) tracked incrementally across the m-loop: one division per thread.
// -------------------------------------------------------------------------
__global__ __launch_bounds__(256) void gather_kernel(float* __restrict__ out)
{
    __shared__ float T[10 * SDIM];
    const int b    = blockIdx.y;
    const int k0   = blockIdx.x << 10;                   // 1024 k per block
    const int kend = min(k0 + 1024, OUTPB);
    const int r_first = k0 / 127;
    const int r_last  = (kend - 1) / 127;
    const int nstage  = (r_last - r_first + 1) * SDIM;

    const float* Sg = g_S + (size_t)b * SDIM * SDIM + (size_t)r_first * SDIM;
    for (int idx = threadIdx.x; idx < nstage; idx += 256)
        T[idx] = Sg[idx] + Sg[idx + SDIM];
    __syncthreads();

    float* ob = out + (size_t)b * OUTPB;

    int k  = k0 + threadIdx.x;
    int r  = k / 127;                                    // one division total
    int cp = k - r * 127;

    #pragma unroll
    for (int m = 0; m < 4; ++m) {
        if (k < kend) {
            const int c = cp + (cp >= r ? 1 : 0);
            const float* Trow = T + (r - r_first) * SDIM;
            ob[k] = Trow[c] + Trow[c + 1];
        }
        // k += 256 == 2*127 + 2  ->  r += 2, cp += 2 (one wrap max)
        k += 256; r += 2; cp += 2;
        if (cp >= 127) { cp -= 127; ++r; }
    }
}

// -------------------------------------------------------------------------
extern "C" void kernel_launch(void* const* d_in, const int* in_sizes, int n_in,
                              void* d_out, int out_size)
{
    const float* xyz = (const float*)d_in[0];
    int B = in_sizes[0] / (NA * 3);
    if (B > MAXB) B = MAXB;

    dim3 gw(8, B);                      // 8 blocks x 8 warps = 64 warps (63 used)
    writhe_kernel<<<gw, 256>>>(xyz);

    dim3 gg(16, B);                     // 16 x 1024 k-chunks
    gather_kernel<<<gg, 256>>>((float*)d_out);
}

// round 17
// speedup vs baseline: 1.4603x; 1.0290x over previous
#include <cuda_runtime.h>

// Problem constants (N_ATOMS = 128, fixed by the reference)
#define NA      128
#define NSEG    7875          // sum_{i=0}^{124} (125 - i)
#define OUTPB   16256         // n^2 - n  (all off-diagonal cells, row-major)
#define MAXB    512
#define SDIM    130           // padded symmetric matrix, zero border (520B rows: benign L2 hash)

// Scratch: per-batch padded symmetric segment-writhe matrix (~34.6 MB).
// Zero-initialized at module load. writhe writes valid (|i-j|>=2) cells in
// BOTH triangles; all other cells stay 0 forever.
__device__ float g_S[(size_t)MAXB * SDIM * SDIM];

// Branch-free asin via Abramowitz & Stegun 4.4.45 (|eps| <= 6.8e-5 abs).
// Saturates for |x| slightly > 1 (om < 0 -> s ~ 0 -> +-pi/2): no clamp needed.
__device__ __forceinline__ float fast_asin(float x)
{
    const float a = fabsf(x);
    float p = fmaf(a, -0.0187293f, 0.0742610f);
    p = fmaf(a, p, -0.2121144f);
    p = fmaf(a, p,  1.5707288f);
    const float om = fmaxf(1.0f - a, 1e-38f);
    const float s  = om * rsqrtf(om);                // sqrt(om) via MUFU
    return copysignf(1.5707963268f - s * p, x);
}

// -------------------------------------------------------------------------
// Kernel 1: writhe, 4 chained segments per thread (one row, j0..j0+3).
// Warp packing: warp 0 <-> row 0 (exactly 32 quads); warp p (1..62) packs
// rows (p, 125-p) whose quad counts sum to exactly 32. 63 warps per batch.
// Chain identities per j -> j+1:  d0 <- d1, d2 <- d3, c3 <- -c1, r3 <- r1.
// -------------------------------------------------------------------------
__global__ __launch_bounds__(256) void writhe_kernel(const float* __restrict__ xyz)
{
    __shared__ float4 pt[NA];
    const int b = blockIdx.y;
    const float* x = xyz + (size_t)b * NA * 3;
    for (int t = threadIdx.x; t < NA; t += blockDim.x)
        pt[t] = make_float4(x[3 * t + 0], x[3 * t + 1], x[3 * t + 2], 0.0f);
    __syncthreads();

    const int warp = threadIdx.x >> 5;
    const int lane = threadIdx.x & 31;
    const int p    = blockIdx.x * 8 + warp;          // 0..63; 63 is empty
    if (p > 62) return;

    const int iA = p;
    const int iB = (p == 0) ? 0 : (125 - p);
    const int qA = (125 - iA + 3) >> 2;              // quads in row A (<=32)

    const bool inA = (lane < qA);
    const int  i   = inA ? iA : iB;
    const int  m   = inA ? lane : (lane - qA);
    const int  j0  = i + 2 + 4 * m;

    const float4 Q0 = pt[i];
    const float4 Q1 = pt[i + 1];
    float4 Pj[5];
    #pragma unroll
    for (int k = 0; k < 5; ++k) Pj[k] = pt[min(j0 + k, 127)];

    // chain state: d0 = P_j - P_i, d2 = P_j - P_{i+1}, c3 = d2 x d0
    float d0x = Pj[0].x - Q0.x, d0y = Pj[0].y - Q0.y, d0z = Pj[0].z - Q0.z;
    float d2x = Pj[0].x - Q1.x, d2y = Pj[0].y - Q1.y, d2z = Pj[0].z - Q1.z;
    float c3x = d2y * d0z - d2z * d0y;
    float c3y = d2z * d0x - d2x * d0z;
    float c3z = d2x * d0y - d2y * d0x;
    float r3  = rsqrtf(c3x * c3x + c3y * c3y + c3z * c3z);

    float* S = g_S + (size_t)b * SDIM * SDIM;

    #pragma unroll
    for (int k = 0; k < 4; ++k) {
        const int j = j0 + k;
        const float4 Pn = Pj[k + 1];

        const float d1x = Pn.x - Q0.x, d1y = Pn.y - Q0.y, d1z = Pn.z - Q0.z;
        const float d3x = Pn.x - Q1.x, d3y = Pn.y - Q1.y, d3z = Pn.z - Q1.z;

        // c0 = d0 x d1, c1 = d1 x d3, c2 = d3 x d2
        const float c0x = d0y * d1z - d0z * d1y;
        const float c0y = d0z * d1x - d0x * d1z;
        const float c0z = d0x * d1y - d0y * d1x;

        const float c1x = d1y * d3z - d1z * d3y;
        const float c1y = d1z * d3x - d1x * d3z;
        const float c1z = d1x * d3y - d1y * d3x;

        const float c2x = d3y * d2z - d3z * d2y;
        const float c2y = d3z * d2x - d3x * d2z;
        const float c2z = d3x * d2y - d3y * d2x;

        // sign: dot(axial, d0) == -(d2 . c0)
        const float dp = d2x * c0x + d2y * c0y + d2z * c0z;
        const float sg = (dp < 0.0f) ? 1.0f : ((dp > 0.0f) ? -1.0f : 0.0f);

        const float r0 = rsqrtf(c0x * c0x + c0y * c0y + c0z * c0z);
        const float r1 = rsqrtf(c1x * c1x + c1y * c1y + c1z * c1z);
        const float r2 = rsqrtf(c2x * c2x + c2y * c2y + c2z * c2z);

        // no clamps: fast_asin saturates for |q| slightly > 1
        const float q0 = (c0x * c1x + c0y * c1y + c0z * c1z) * r0 * r1;
        const float q1 = (c1x * c2x + c1y * c2y + c1z * c2z) * r1 * r2;
        const float q2 = (c2x * c3x + c2y * c3y + c2z * c3z) * r2 * r3;
        const float q3 = (c3x * c0x + c3y * c0y + c3z * c0z) * r3 * r0;

        const float omega = fast_asin(q0) + fast_asin(q1) +
                            fast_asin(q2) + fast_asin(q3);
        const float wr = omega * sg * 0.15915494309189535f; // 1/(2*pi)

        if (j <= 126) {
            S[(i + 1) * SDIM + (j + 1)] = wr;
            S[(j + 1) * SDIM + (i + 1)] = wr;
        }

        // rotate chain state
        d0x = d1x;  d0y = d1y;  d0z = d1z;
        d2x = d3x;  d2y = d3y;  d2z = d3z;
        c3x = -c1x; c3y = -c1y; c3z = -c1z;
        r3  = r1;
    }
}

// -------------------------------------------------------------------------
// Kernel 2: stencil via staged vertical-pair sums.
// Block <-> 1024 consecutive k of one batch. Stage T rows:
//   T_r[c] = S[r][c] + S[r+1][c]     (identical layout -> coalesced staging)
// Then out[k] = T_r[c] + T_r[c+1], threads lane-strided over k.
// (r, cp) tracked incrementally across the m-loop: one division per thread.
// -------------------------------------------------------------------------
__global__ __launch_bounds__(256) void gather_kernel(float* __restrict__ out)
{
    __shared__ float T[10 * SDIM];
    const int b    = blockIdx.y;
    const int k0   = blockIdx.x << 10;                   // 1024 k per block
    const int kend = min(k0 + 1024, OUTPB);
    const int r_first = k0 / 127;
    const int r_last  = (kend - 1) / 127;
    const int nstage  = (r_last - r_first + 1) * SDIM;

    const float* Sg = g_S + (size_t)b * SDIM * SDIM + (size_t)r_first * SDIM;
    for (int idx = threadIdx.x; idx < nstage; idx += 256)
        T[idx] = Sg[idx] + Sg[idx + SDIM];
    __syncthreads();

    float* ob = out + (size_t)b * OUTPB;

    int k  = k0 + threadIdx.x;
    int r  = k / 127;                                    // one division total
    int cp = k - r * 127;

    #pragma unroll
    for (int m = 0; m < 4; ++m) {
        if (k < kend) {
            const int c = cp + (cp >= r ? 1 : 0);
            const float* Trow = T + (r - r_first) * SDIM;
            ob[k] = Trow[c] + Trow[c + 1];
        }
        // k += 256 == 2*127 + 2  ->  r += 2, cp += 2 (one wrap max)
        k += 256; r += 2; cp += 2;
        if (cp >= 127) { cp -= 127; ++r; }
    }
}

// -------------------------------------------------------------------------
extern "C" void kernel_launch(void* const* d_in, const int* in_sizes, int n_in,
                              void* d_out, int out_size)
{
    const float* xyz = (const float*)d_in[0];
    int B = in_sizes[0] / (NA * 3);
    if (B > MAXB) B = MAXB;

    dim3 gw(8, B);                      // 8 blocks x 8 warps = 64 warps (63 used)
    writhe_kernel<<<gw, 256>>>(xyz);

    dim3 gg(16, B);                     // 16 x 1024 k-chunks
    gather_kernel<<<gg, 256>>>((float*)d_out);
}